// round 14
// baseline (speedup 1.0000x reference)
#include <cuda_runtime.h>
#include <cuda_bf16.h>
#include <cstdint>
#include <cstddef>

// Problem: X [8,256,64,64]; three 3x3 SAME convs 256->256; spatial attention.
#define BB 8
#define CC 256
#define HH 64
#define WW 64
#define NNPIX 4096
#define KCONV 2304            // 9 taps * 256 ci

// ======================= scratch (__device__, no allocs) =====================
__device__ __align__(128) float          g_M[134217728];                 // logits fp32 [b][n][m]
__device__ __align__(128) __nv_bfloat16  g_Ph[134217728];                // probs hi  [b][n][m]
__device__ __align__(128) __nv_bfloat16  g_Pl[134217728];                // probs lo
__device__ __align__(128) __nv_bfloat16  g_Xch[75497472];                // im2col hi [b][n][k]
__device__ __align__(128) __nv_bfloat16  g_Xcl[75497472];                // im2col lo
__device__ __align__(128) __nv_bfloat16  g_Ah[8388608], g_Al[8388608];   // feat1 [b][n][c]
__device__ __align__(128) __nv_bfloat16  g_Bh[8388608], g_Bl[8388608];   // feat2 [b][n][c]
__device__ __align__(128) __nv_bfloat16  g_Dh[8388608], g_Dl[8388608];   // feat3 [b][c][n]
__device__ __align__(128) __nv_bfloat16  g_Wh[1769472], g_Wl[1769472];   // [which][co][k]

// ======================= helpers =============================================
__device__ __forceinline__ uint32_t smem_u32(const void* p) {
    uint32_t a;
    asm("{ .reg .u64 t; cvta.to.shared.u64 t, %1; cvt.u32.u64 %0, t; }"
        : "=r"(a) : "l"(p));
    return a;
}
__device__ __forceinline__ void cp16(uint32_t dst, const void* src) {
    asm volatile("cp.async.cg.shared.global [%0], [%1], 16;" :: "r"(dst), "l"(src));
}
#define CP_COMMIT() asm volatile("cp.async.commit_group;" ::: "memory")
#define CP_WAIT(n)  asm volatile("cp.async.wait_group %0;" :: "n"(n) : "memory")

__device__ __forceinline__ void ldsm_x4(uint32_t* r, uint32_t a) {
    asm volatile("ldmatrix.sync.aligned.m8n8.x4.shared.b16 {%0,%1,%2,%3}, [%4];"
        : "=r"(r[0]), "=r"(r[1]), "=r"(r[2]), "=r"(r[3]) : "r"(a));
}
__device__ __forceinline__ void mma_bf16(float* c, const uint32_t* a, const uint32_t* b) {
    asm volatile("mma.sync.aligned.m16n8k16.row.col.f32.bf16.bf16.f32 "
        "{%0,%1,%2,%3}, {%4,%5,%6,%7}, {%8,%9}, {%0,%1,%2,%3};"
        : "+f"(c[0]), "+f"(c[1]), "+f"(c[2]), "+f"(c[3])
        : "r"(a[0]), "r"(a[1]), "r"(a[2]), "r"(a[3]), "r"(b[0]), "r"(b[1]));
}
__device__ __forceinline__ void bsplit(float v, __nv_bfloat16& h, __nv_bfloat16& l) {
    h = __float2bfloat16(v);
    l = __float2bfloat16(v - __bfloat162float(h));
}

// ======================= prep: weights -> [which][co][tap*256+ci] hi/lo ======
__global__ void prep_weights(const float* __restrict__ w1,
                             const float* __restrict__ w2,
                             const float* __restrict__ w3) {
    int idx = blockIdx.x * 256 + threadIdx.x;      // < 3*589824
    int which = idx / 589824;
    int r     = idx % 589824;
    int co    = r / KCONV;
    int k     = r % KCONV;
    int tap   = k / 256;
    int ci    = k % 256;
    const float* w = (which == 0) ? w1 : (which == 1) ? w2 : w3;
    float v = w[(co * 256 + ci) * 9 + tap];
    bsplit(v, g_Wh[idx], g_Wl[idx]);
}

// ======================= prep: im2col hi/lo bf16 [b][n][tap*256+ci] ==========
__global__ void im2col_kernel(const float* __restrict__ X) {
    __shared__ float Xs[32][3][65];
    int y  = blockIdx.x;
    int c0 = blockIdx.y * 32;
    int b  = blockIdx.z;
    int tid = threadIdx.x;

    for (int i = tid; i < 32 * 3 * 64; i += 256) {
        int ci  = i / 192;
        int rem = i % 192;
        int r   = rem / 64;
        int x   = rem % 64;
        int yy  = y + r - 1;
        float v = 0.0f;
        if (yy >= 0 && yy < HH)
            v = X[((size_t)(b * CC + c0 + ci)) * NNPIX + yy * WW + x];
        Xs[ci][r][x] = v;
    }
    __syncthreads();

    for (int t = 0; t < 9; ++t) {
        int dy = t / 3, dx = t % 3 - 1;
        for (int i = tid; i < 2048; i += 256) {
            int ci = i & 31;
            int x  = i >> 5;
            int px = x + dx;
            float v = (px >= 0 && px < WW) ? Xs[ci][dy][px] : 0.0f;
            size_t o = ((size_t)(b * NNPIX + y * WW + x)) * KCONV + t * 256 + c0 + ci;
            bsplit(v, g_Xch[o], g_Xcl[o]);
        }
    }
}

// ======================= operand selectors ===================================
__device__ __forceinline__ const __nv_bfloat16* sel_h(int s) {
    switch (s) {
        case 0: return g_Wh;  case 1: return g_Xch; case 2: return g_Ah;
        case 3: return g_Bh;  case 4: return g_Dh;  default: return g_Ph;
    }
}
__device__ __forceinline__ const __nv_bfloat16* sel_l(int s) {
    switch (s) {
        case 0: return g_Wl;  case 1: return g_Xcl; case 2: return g_Al;
        case 3: return g_Bl;  case 4: return g_Dl;  default: return g_Pl;
    }
}
__device__ __forceinline__ __nv_bfloat16* sel_oh(int s) {
    return (s == 0) ? g_Ah : (s == 1) ? g_Bh : g_Dh;
}
__device__ __forceinline__ __nv_bfloat16* sel_ol(int s) {
    return (s == 0) ? g_Al : (s == 1) ? g_Bl : g_Dl;
}

// ======================= unified bf16 mma.sync GEMM ==========================
// D[m][n] = sum_k Aop[m][k] * Bop[n][k]  (both operands K-major), 3-pass hi/lo.
// Block tile 128x64, BK=64, 8 warps (4x2 -> 32x32 warp tiles), cp.async x2
// stages, 2 CTAs/SM (smem 108KB/CTA, regs capped at 128).
// MODE 0: feat epilogue  (+bias[col], bf16 hi/lo out)   conv1/conv2
// MODE 1: featD epilogue (+bias[row], bf16 hi/lo out)   conv3
// MODE 2: logits epilogue (fp32 -> g_M)
// MODE 3: final epilogue  (fp32 * alpha -> outf)
#define TILEA   18432           // 128 rows * 144B (64 bf16 + 16B pad)
#define TILEBT  9216            // 64 rows * 144B
#define STAGEB  (2 * TILEA + 2 * TILEBT)   // 55296
#define GSMEM   (2 * STAGEB)               // 110592

template <int MODE>
__global__ void __launch_bounds__(256, 2)
gemm_mma(int asel, long long a_off, long a_rs, long long a_bs,
         int bsel, long long b_off, long b_rs, long long b_bs,
         int Ktot, int osel, long long o_bs, int ldo,
         float* outf, const float* __restrict__ bias)
{
    extern __shared__ char smem[];
    uint32_t sb = smem_u32(smem);
    int tid  = threadIdx.x;
    int wid  = tid >> 5, lane = tid & 31;
    int g    = lane >> 2, tig = lane & 3;
    int wm   = (wid >> 1) * 32;       // warp m-offset (4 rows of warps)
    int wn   = (wid & 1) * 32;        // warp n-offset (2 cols)

    int bn0 = blockIdx.x * 64;
    int bm0 = blockIdx.y * 128;
    int b   = blockIdx.z;

    const __nv_bfloat16* pAh = sel_h(asel) + a_off + (size_t)b * a_bs + (size_t)bm0 * a_rs;
    const __nv_bfloat16* pAl = sel_l(asel) + a_off + (size_t)b * a_bs + (size_t)bm0 * a_rs;
    const __nv_bfloat16* pBh = sel_h(bsel) + b_off + (size_t)b * b_bs + (size_t)bn0 * b_rs;
    const __nv_bfloat16* pBl = sel_l(bsel) + b_off + (size_t)b * b_bs + (size_t)bn0 * b_rs;

    float acc[2][4][4] = {};
    const int NC = Ktot >> 6;

    // ---- stage loader: 64 bf16 = 128B per row in 8x16B chunks ----
    auto stage_load = [&](int s, int kc) {
        uint32_t base = sb + s * STAGEB;
        #pragma unroll
        for (int i = 0; i < 4; ++i) {
            int u   = tid + i * 256;          // 0..1023
            int row = u >> 3;
            int ch  = u & 7;
            size_t ka = (size_t)row * a_rs + kc + ch * 8;
            uint32_t d = base + row * 144 + ch * 16;
            cp16(d,         pAh + ka);
            cp16(d + TILEA, pAl + ka);
        }
        #pragma unroll
        for (int i = 0; i < 2; ++i) {
            int u   = tid + i * 256;          // 0..511
            int row = u >> 3;                 // 0..63
            int ch  = u & 7;
            size_t kb = (size_t)row * b_rs + kc + ch * 8;
            uint32_t d = base + 2 * TILEA + row * 144 + ch * 16;
            cp16(d,          pBh + kb);
            cp16(d + TILEBT, pBl + kb);
        }
    };

    stage_load(0, 0);
    CP_COMMIT();

    // A ldsm: m16k16 frags. B ldsm: paired-j x4 (two n8k16 frags per x4).
    uint32_t arow = (wm + (lane & 15)) * 144 + ((lane >> 4) << 4);
    uint32_t brow = (wn + ((lane >> 4) << 3) + (lane & 7)) * 144 + (((lane >> 3) & 1) << 4);

    for (int c = 0; c < NC; ++c) {
        if (c + 1 < NC) {
            stage_load((c + 1) & 1, (c + 1) * 64);
            CP_COMMIT();
            CP_WAIT(1);
        } else {
            CP_WAIT(0);
        }
        __syncthreads();

        uint32_t Ab = sb + (c & 1) * STAGEB;
        uint32_t Bb = Ab + 2 * TILEA;

        #pragma unroll
        for (int ks = 0; ks < 4; ++ks) {
            uint32_t bh[2][4], bl[2][4];
            #pragma unroll
            for (int jp = 0; jp < 2; ++jp) {
                uint32_t ra = Bb + brow + jp * (16 * 144) + ks * 32;
                ldsm_x4(bh[jp], ra);
                ldsm_x4(bl[jp], ra + TILEBT);
            }
            #pragma unroll
            for (int i = 0; i < 2; ++i) {
                uint32_t ah[4], al[4];
                uint32_t ra = Ab + arow + i * (16 * 144) + ks * 32;
                ldsm_x4(ah, ra);
                ldsm_x4(al, ra + TILEA);
                #pragma unroll
                for (int j = 0; j < 4; ++j) {
                    const uint32_t* ph = &bh[j >> 1][(j & 1) * 2];
                    const uint32_t* pl = &bl[j >> 1][(j & 1) * 2];
                    mma_bf16(acc[i][j], ah, ph);   // hi*hi
                    mma_bf16(acc[i][j], ah, pl);   // hi*lo
                    mma_bf16(acc[i][j], al, ph);   // lo*hi
                }
            }
        }
        __syncthreads();
    }

    // ---- epilogue ----
    const float alpha = (MODE == 3) ? bias[0] : 1.0f;
    __nv_bfloat16* oh = (MODE <= 1) ? sel_oh(osel) : (__nv_bfloat16*)0;
    __nv_bfloat16* ol = (MODE <= 1) ? sel_ol(osel) : (__nv_bfloat16*)0;
    float* ofp = (MODE == 2) ? g_M : outf;
    size_t ob = (size_t)b * o_bs;

    #pragma unroll
    for (int i = 0; i < 2; ++i) {
        int row = bm0 + wm + i * 16 + g;
        float br0 = 0.0f, br1 = 0.0f;
        if (MODE == 1) { br0 = bias[row]; br1 = bias[row + 8]; }
        #pragma unroll
        for (int j = 0; j < 4; ++j) {
            int col = bn0 + wn + j * 8 + tig * 2;
            float v00 = acc[i][j][0], v01 = acc[i][j][1];
            float v10 = acc[i][j][2], v11 = acc[i][j][3];
            if (MODE == 0) {
                float bc0 = bias[col], bc1 = bias[col + 1];
                v00 += bc0; v01 += bc1; v10 += bc0; v11 += bc1;
            } else if (MODE == 1) {
                v00 += br0; v01 += br0; v10 += br1; v11 += br1;
            }
            size_t o0 = ob + (size_t)row * ldo + col;
            size_t o1 = o0 + (size_t)8 * ldo;
            if (MODE >= 2) {
                *(float2*)(ofp + o0) = make_float2(alpha * v00, alpha * v01);
                *(float2*)(ofp + o1) = make_float2(alpha * v10, alpha * v11);
            } else {
                __nv_bfloat16 h0, l0, h1, l1;
                bsplit(v00, h0, l0); bsplit(v01, h1, l1);
                *(__nv_bfloat162*)(oh + o0) = __nv_bfloat162(h0, h1);
                *(__nv_bfloat162*)(ol + o0) = __nv_bfloat162(l0, l1);
                bsplit(v10, h0, l0); bsplit(v11, h1, l1);
                *(__nv_bfloat162*)(oh + o1) = __nv_bfloat162(h0, h1);
                *(__nv_bfloat162*)(ol + o1) = __nv_bfloat162(l0, l1);
            }
        }
    }
}

// ======================= softmax: g_M row -> Ph/Pl bf16 ======================
__global__ void softmax_kernel() {
    __shared__ float red[32];
    size_t row = blockIdx.x;
    const float4* p = (const float4*)(g_M + row * (size_t)NNPIX);

    int tid  = threadIdx.x;
    int lane = tid & 31;
    int warp = tid >> 5;

    float4 v[4];
    #pragma unroll
    for (int i = 0; i < 4; ++i) v[i] = p[i * 256 + tid];

    float mx = -1e30f;
    #pragma unroll
    for (int i = 0; i < 4; ++i)
        mx = fmaxf(mx, fmaxf(fmaxf(v[i].x, v[i].y), fmaxf(v[i].z, v[i].w)));
    #pragma unroll
    for (int o = 16; o > 0; o >>= 1)
        mx = fmaxf(mx, __shfl_xor_sync(0xffffffffu, mx, o));
    if (lane == 0) red[warp] = mx;
    __syncthreads();
    if (tid < 32) {
        float m = (tid < 8) ? red[tid] : -1e30f;
        #pragma unroll
        for (int o = 4; o > 0; o >>= 1)
            m = fmaxf(m, __shfl_xor_sync(0xffffffffu, m, o));
        if (tid == 0) red[0] = m;
    }
    __syncthreads();
    mx = red[0];
    __syncthreads();

    float s = 0.0f;
    #pragma unroll
    for (int i = 0; i < 4; ++i) {
        v[i].x = __expf(v[i].x - mx);
        v[i].y = __expf(v[i].y - mx);
        v[i].z = __expf(v[i].z - mx);
        v[i].w = __expf(v[i].w - mx);
        s += v[i].x + v[i].y + v[i].z + v[i].w;
    }
    #pragma unroll
    for (int o = 16; o > 0; o >>= 1)
        s += __shfl_xor_sync(0xffffffffu, s, o);
    if (lane == 0) red[warp] = s;
    __syncthreads();
    if (tid < 32) {
        float t = (tid < 8) ? red[tid] : 0.0f;
        #pragma unroll
        for (int o = 4; o > 0; o >>= 1)
            t += __shfl_xor_sync(0xffffffffu, t, o);
        if (tid == 0) red[0] = t;
    }
    __syncthreads();
    float rs = 1.0f / red[0];

    #pragma unroll
    for (int i = 0; i < 4; ++i) {
        size_t base = row * (size_t)NNPIX + i * 1024 + tid * 4;
        float pv[4] = {v[i].x * rs, v[i].y * rs, v[i].z * rs, v[i].w * rs};
        __nv_bfloat16 h[4], l[4];
        #pragma unroll
        for (int q = 0; q < 4; ++q) bsplit(pv[q], h[q], l[q]);
        *(__nv_bfloat162*)(g_Ph + base)     = __nv_bfloat162(h[0], h[1]);
        *(__nv_bfloat162*)(g_Ph + base + 2) = __nv_bfloat162(h[2], h[3]);
        *(__nv_bfloat162*)(g_Pl + base)     = __nv_bfloat162(l[0], l[1]);
        *(__nv_bfloat162*)(g_Pl + base + 2) = __nv_bfloat162(l[2], l[3]);
    }
}

// ======================= launch ==============================================
extern "C" void kernel_launch(void* const* d_in, const int* in_sizes, int n_in,
                              void* d_out, int out_size) {
    const float* X     = (const float*)d_in[0];
    const float* w1    = (const float*)d_in[1];
    const float* b1    = (const float*)d_in[2];
    const float* w2    = (const float*)d_in[3];
    const float* b2    = (const float*)d_in[4];
    const float* w3    = (const float*)d_in[5];
    const float* b3    = (const float*)d_in[6];
    const float* alpha = (const float*)d_in[7];
    float* out = (float*)d_out;

    cudaFuncSetAttribute(gemm_mma<0>, cudaFuncAttributeMaxDynamicSharedMemorySize, GSMEM);
    cudaFuncSetAttribute(gemm_mma<1>, cudaFuncAttributeMaxDynamicSharedMemorySize, GSMEM);
    cudaFuncSetAttribute(gemm_mma<2>, cudaFuncAttributeMaxDynamicSharedMemorySize, GSMEM);
    cudaFuncSetAttribute(gemm_mma<3>, cudaFuncAttributeMaxDynamicSharedMemorySize, GSMEM);

    prep_weights<<<6912, 256>>>(w1, w2, w3);
    im2col_kernel<<<dim3(64, 8, 8), 256>>>(X);

    // conv1: M=pix (im2col rows), N=co (weight rows) -> feat1 [b][pix][co]
    gemm_mma<0><<<dim3(4, 32, 8), 256, GSMEM>>>(
        1, 0LL, KCONV, 9437184LL,     0, 0LL,       KCONV, 0LL,
        KCONV, 0, 1048576LL, 256, nullptr, b1);
    // conv2 -> feat2 [b][pix][co]
    gemm_mma<0><<<dim3(4, 32, 8), 256, GSMEM>>>(
        1, 0LL, KCONV, 9437184LL,     0, 589824LL,  KCONV, 0LL,
        KCONV, 1, 1048576LL, 256, nullptr, b2);
    // conv3: M=co, N=pix -> feat3 [b][co][pix]
    gemm_mma<1><<<dim3(64, 2, 8), 256, GSMEM>>>(
        0, 1179648LL, KCONV, 0LL,     1, 0LL,       KCONV, 9437184LL,
        KCONV, 2, 1048576LL, 4096, nullptr, b3);

    // logits: S[n][m] = sum_c feat1[n][c] * feat2[m][c]
    gemm_mma<2><<<dim3(64, 32, 8), 256, GSMEM>>>(
        2, 0LL, 256, 1048576LL,       3, 0LL,       256,   1048576LL,
        256, 0, 16777216LL, 4096, nullptr, nullptr);

    softmax_kernel<<<BB * NNPIX, 256>>>();

    // final: out[c][n] = alpha * sum_m D[c][m] * P[n][m]
    gemm_mma<3><<<dim3(64, 2, 8), 256, GSMEM>>>(
        4, 0LL, 4096, 1048576LL,      5, 0LL,       4096,  16777216LL,
        4096, 0, 1048576LL, 4096, out, alpha);
}

// round 15
// speedup vs baseline: 1.2972x; 1.2972x over previous
#include <cuda_runtime.h>
#include <cuda_bf16.h>
#include <cstdint>
#include <cstddef>

// Problem: X [8,256,64,64]; three 3x3 SAME convs 256->256; spatial attention.
#define BB 8
#define CC 256
#define HH 64
#define WW 64
#define NNPIX 4096
#define KCONV 2304            // 9 taps * 256 ci

// ======================= scratch (__device__, no allocs) =====================
__device__ __align__(128) float          g_M[134217728];                 // logits fp32 [b][n][m]
__device__ __align__(128) __nv_bfloat16  g_Ph[134217728];                // probs hi  [b][n][m]
__device__ __align__(128) __nv_bfloat16  g_Pl[134217728];                // probs lo
__device__ __align__(128) __nv_bfloat16  g_Xch[75497472];                // im2col hi [b][n][k]
__device__ __align__(128) __nv_bfloat16  g_Xcl[75497472];                // im2col lo
__device__ __align__(128) __nv_bfloat16  g_Ah[8388608], g_Al[8388608];   // feat1 [b][n][c]
__device__ __align__(128) __nv_bfloat16  g_Bh[8388608], g_Bl[8388608];   // feat2 [b][n][c]
__device__ __align__(128) __nv_bfloat16  g_Dh[8388608], g_Dl[8388608];   // feat3 [b][c][n]
__device__ __align__(128) __nv_bfloat16  g_Wh[1769472], g_Wl[1769472];   // [which][co][k]

// ======================= helpers =============================================
__device__ __forceinline__ uint32_t smem_u32(const void* p) {
    uint32_t a;
    asm("{ .reg .u64 t; cvta.to.shared.u64 t, %1; cvt.u32.u64 %0, t; }"
        : "=r"(a) : "l"(p));
    return a;
}
__device__ __forceinline__ void cp16(uint32_t dst, const void* src) {
    asm volatile("cp.async.cg.shared.global [%0], [%1], 16;" :: "r"(dst), "l"(src));
}
#define CP_COMMIT() asm volatile("cp.async.commit_group;" ::: "memory")
#define CP_WAIT(n)  asm volatile("cp.async.wait_group %0;" :: "n"(n) : "memory")

__device__ __forceinline__ void ldsm_x4(uint32_t* r, uint32_t a) {
    asm volatile("ldmatrix.sync.aligned.m8n8.x4.shared.b16 {%0,%1,%2,%3}, [%4];"
        : "=r"(r[0]), "=r"(r[1]), "=r"(r[2]), "=r"(r[3]) : "r"(a));
}
__device__ __forceinline__ void ldsm_x2(uint32_t* r, uint32_t a) {
    asm volatile("ldmatrix.sync.aligned.m8n8.x2.shared.b16 {%0,%1}, [%2];"
        : "=r"(r[0]), "=r"(r[1]) : "r"(a));
}
__device__ __forceinline__ void mma_bf16(float* c, const uint32_t* a, const uint32_t* b) {
    asm volatile("mma.sync.aligned.m16n8k16.row.col.f32.bf16.bf16.f32 "
        "{%0,%1,%2,%3}, {%4,%5,%6,%7}, {%8,%9}, {%0,%1,%2,%3};"
        : "+f"(c[0]), "+f"(c[1]), "+f"(c[2]), "+f"(c[3])
        : "r"(a[0]), "r"(a[1]), "r"(a[2]), "r"(a[3]), "r"(b[0]), "r"(b[1]));
}
__device__ __forceinline__ void bsplit(float v, __nv_bfloat16& h, __nv_bfloat16& l) {
    h = __float2bfloat16(v);
    l = __float2bfloat16(v - __bfloat162float(h));
}

// ======================= prep: weights -> [which][co][tap*256+ci] hi/lo ======
__global__ void prep_weights(const float* __restrict__ w1,
                             const float* __restrict__ w2,
                             const float* __restrict__ w3) {
    int idx = blockIdx.x * 256 + threadIdx.x;      // < 3*589824
    int which = idx / 589824;
    int r     = idx % 589824;
    int co    = r / KCONV;
    int k     = r % KCONV;
    int tap   = k / 256;
    int ci    = k % 256;
    const float* w = (which == 0) ? w1 : (which == 1) ? w2 : w3;
    float v = w[(co * 256 + ci) * 9 + tap];
    bsplit(v, g_Wh[idx], g_Wl[idx]);
}

// ======================= prep: im2col hi/lo bf16 [b][n][tap*256+ci] ==========
__global__ void im2col_kernel(const float* __restrict__ X) {
    __shared__ float Xs[32][3][65];
    int y  = blockIdx.x;
    int c0 = blockIdx.y * 32;
    int b  = blockIdx.z;
    int tid = threadIdx.x;

    for (int i = tid; i < 32 * 3 * 64; i += 256) {
        int ci  = i / 192;
        int rem = i % 192;
        int r   = rem / 64;
        int x   = rem % 64;
        int yy  = y + r - 1;
        float v = 0.0f;
        if (yy >= 0 && yy < HH)
            v = X[((size_t)(b * CC + c0 + ci)) * NNPIX + yy * WW + x];
        Xs[ci][r][x] = v;
    }
    __syncthreads();

    for (int t = 0; t < 9; ++t) {
        int dy = t / 3, dx = t % 3 - 1;
        for (int i = tid; i < 2048; i += 256) {
            int ci = i & 31;
            int x  = i >> 5;
            int px = x + dx;
            float v = (px >= 0 && px < WW) ? Xs[ci][dy][px] : 0.0f;
            size_t o = ((size_t)(b * NNPIX + y * WW + x)) * KCONV + t * 256 + c0 + ci;
            bsplit(v, g_Xch[o], g_Xcl[o]);
        }
    }
}

// ======================= operand selectors ===================================
__device__ __forceinline__ const __nv_bfloat16* sel_h(int s) {
    switch (s) {
        case 0: return g_Wh;  case 1: return g_Xch; case 2: return g_Ah;
        case 3: return g_Bh;  case 4: return g_Dh;  default: return g_Ph;
    }
}
__device__ __forceinline__ const __nv_bfloat16* sel_l(int s) {
    switch (s) {
        case 0: return g_Wl;  case 1: return g_Xcl; case 2: return g_Al;
        case 3: return g_Bl;  case 4: return g_Dl;  default: return g_Pl;
    }
}
__device__ __forceinline__ __nv_bfloat16* sel_oh(int s) {
    return (s == 0) ? g_Ah : (s == 1) ? g_Bh : g_Dh;
}
__device__ __forceinline__ __nv_bfloat16* sel_ol(int s) {
    return (s == 0) ? g_Al : (s == 1) ? g_Bl : g_Dl;
}

// ======================= unified bf16 mma.sync GEMM ==========================
// D[m][n] = sum_k Aop[m][k] * Bop[n][k]  (both operands K-major), 3-pass hi/lo.
// Block tile 128x64, BK=32, 8 warps (4x2 -> 32x32 warp tiles), cp.async x3
// stages with ONE __syncthreads per chunk, 2 CTAs/SM (smem 92KB/CTA).
// MODE 0: feat epilogue  (+bias[col], bf16 hi/lo out)   conv1/conv2
// MODE 1: featD epilogue (+bias[row], bf16 hi/lo out)   conv3
// MODE 2: logits epilogue (fp32 -> g_M)
// MODE 3: final epilogue  (fp32 * alpha -> outf)
#define TILEA   10240           // 128 rows * 80B (32 bf16 + 16B pad)
#define TILEBT  5120            // 64 rows * 80B
#define STAGEB  (2 * TILEA + 2 * TILEBT)   // 30720
#define NSTAGE  3
#define GSMEM   (NSTAGE * STAGEB)          // 92160

template <int MODE>
__global__ void __launch_bounds__(256, 2)
gemm_mma(int asel, long long a_off, long a_rs, long long a_bs,
         int bsel, long long b_off, long b_rs, long long b_bs,
         int Ktot, int osel, long long o_bs, int ldo,
         float* outf, const float* __restrict__ bias)
{
    extern __shared__ char smem[];
    uint32_t sb = smem_u32(smem);
    int tid  = threadIdx.x;
    int wid  = tid >> 5, lane = tid & 31;
    int g    = lane >> 2, tig = lane & 3;
    int wm   = (wid >> 1) * 32;       // warp m-offset (4 rows of warps)
    int wn   = (wid & 1) * 32;        // warp n-offset (2 cols)

    int bn0 = blockIdx.x * 64;
    int bm0 = blockIdx.y * 128;
    int b   = blockIdx.z;

    const __nv_bfloat16* pAh = sel_h(asel) + a_off + (size_t)b * a_bs + (size_t)bm0 * a_rs;
    const __nv_bfloat16* pAl = sel_l(asel) + a_off + (size_t)b * a_bs + (size_t)bm0 * a_rs;
    const __nv_bfloat16* pBh = sel_h(bsel) + b_off + (size_t)b * b_bs + (size_t)bn0 * b_rs;
    const __nv_bfloat16* pBl = sel_l(bsel) + b_off + (size_t)b * b_bs + (size_t)bn0 * b_rs;

    float acc[2][4][4] = {};
    const int NC = Ktot >> 5;

    // ---- stage loader: A 2x512 chunks, B 2x256 chunks (16B each) ----
    auto stage_load = [&](int s, int kc) {
        uint32_t base = sb + s * STAGEB;
        #pragma unroll
        for (int i = 0; i < 2; ++i) {
            int u   = tid + i * 256;          // 0..511
            int row = u >> 2;
            int ch  = u & 3;
            size_t ka = (size_t)row * a_rs + kc + ch * 8;
            uint32_t d = base + row * 80 + ch * 16;
            cp16(d,         pAh + ka);
            cp16(d + TILEA, pAl + ka);
        }
        {
            int row = tid >> 2;               // 0..63
            int ch  = tid & 3;
            size_t kb = (size_t)row * b_rs + kc + ch * 8;
            uint32_t d = base + 2 * TILEA + row * 80 + ch * 16;
            cp16(d,          pBh + kb);
            cp16(d + TILEBT, pBl + kb);
        }
    };

    // prefetch two stages
    stage_load(0, 0);
    CP_COMMIT();
    if (NC > 1) { stage_load(1, 32); CP_COMMIT(); }

    uint32_t arow = (wm + (lane & 15)) * 80 + ((lane >> 4) * 16);
    uint32_t brow = (wn + (lane & 7)) * 80 + (((lane >> 3) & 1) * 16);

    int slot = 0;
    for (int c = 0; c < NC; ++c) {
        if (c + 1 < NC) { CP_WAIT(1); } else { CP_WAIT(0); }
        __syncthreads();                       // stage c ready; all warps done with c-1

        if (c + 2 < NC) {                      // refill slot holding stage c-1
            int ns = slot + 2; if (ns >= NSTAGE) ns -= NSTAGE;
            stage_load(ns, (c + 2) * 32);
            CP_COMMIT();
        }

        uint32_t Ab = sb + slot * STAGEB;
        uint32_t Bb = Ab + 2 * TILEA;

        #pragma unroll
        for (int ks = 0; ks < 2; ++ks) {
            uint32_t bh[4][2], bl[4][2];
            #pragma unroll
            for (int j = 0; j < 4; ++j) {
                uint32_t ra = Bb + brow + j * (8 * 80) + ks * 32;
                ldsm_x2(bh[j], ra);
                ldsm_x2(bl[j], ra + TILEBT);
            }
            #pragma unroll
            for (int i = 0; i < 2; ++i) {
                uint32_t ah[4], al[4];
                uint32_t ra = Ab + arow + i * (16 * 80) + ks * 32;
                ldsm_x4(ah, ra);
                ldsm_x4(al, ra + TILEA);
                #pragma unroll
                for (int j = 0; j < 4; ++j) {
                    mma_bf16(acc[i][j], ah, bh[j]);   // hi*hi
                    mma_bf16(acc[i][j], ah, bl[j]);   // hi*lo
                    mma_bf16(acc[i][j], al, bh[j]);   // lo*hi
                }
            }
        }

        if (++slot == NSTAGE) slot = 0;
    }

    // ---- epilogue ----
    const float alpha = (MODE == 3) ? bias[0] : 1.0f;
    __nv_bfloat16* oh = (MODE <= 1) ? sel_oh(osel) : (__nv_bfloat16*)0;
    __nv_bfloat16* ol = (MODE <= 1) ? sel_ol(osel) : (__nv_bfloat16*)0;
    float* ofp = (MODE == 2) ? g_M : outf;
    size_t ob = (size_t)b * o_bs;

    #pragma unroll
    for (int i = 0; i < 2; ++i) {
        int row = bm0 + wm + i * 16 + g;
        float br0 = 0.0f, br1 = 0.0f;
        if (MODE == 1) { br0 = bias[row]; br1 = bias[row + 8]; }
        #pragma unroll
        for (int j = 0; j < 4; ++j) {
            int col = bn0 + wn + j * 8 + tig * 2;
            float v00 = acc[i][j][0], v01 = acc[i][j][1];
            float v10 = acc[i][j][2], v11 = acc[i][j][3];
            if (MODE == 0) {
                float bc0 = bias[col], bc1 = bias[col + 1];
                v00 += bc0; v01 += bc1; v10 += bc0; v11 += bc1;
            } else if (MODE == 1) {
                v00 += br0; v01 += br0; v10 += br1; v11 += br1;
            }
            size_t o0 = ob + (size_t)row * ldo + col;
            size_t o1 = o0 + (size_t)8 * ldo;
            if (MODE >= 2) {
                *(float2*)(ofp + o0) = make_float2(alpha * v00, alpha * v01);
                *(float2*)(ofp + o1) = make_float2(alpha * v10, alpha * v11);
            } else {
                __nv_bfloat16 h0, l0, h1, l1;
                bsplit(v00, h0, l0); bsplit(v01, h1, l1);
                *(__nv_bfloat162*)(oh + o0) = __nv_bfloat162(h0, h1);
                *(__nv_bfloat162*)(ol + o0) = __nv_bfloat162(l0, l1);
                bsplit(v10, h0, l0); bsplit(v11, h1, l1);
                *(__nv_bfloat162*)(oh + o1) = __nv_bfloat162(h0, h1);
                *(__nv_bfloat162*)(ol + o1) = __nv_bfloat162(l0, l1);
            }
        }
    }
}

// ======================= softmax: g_M row -> Ph/Pl bf16 ======================
__global__ void softmax_kernel() {
    __shared__ float red[32];
    size_t row = blockIdx.x;
    const float4* p = (const float4*)(g_M + row * (size_t)NNPIX);

    int tid  = threadIdx.x;
    int lane = tid & 31;
    int warp = tid >> 5;

    float4 v[4];
    #pragma unroll
    for (int i = 0; i < 4; ++i) v[i] = p[i * 256 + tid];

    float mx = -1e30f;
    #pragma unroll
    for (int i = 0; i < 4; ++i)
        mx = fmaxf(mx, fmaxf(fmaxf(v[i].x, v[i].y), fmaxf(v[i].z, v[i].w)));
    #pragma unroll
    for (int o = 16; o > 0; o >>= 1)
        mx = fmaxf(mx, __shfl_xor_sync(0xffffffffu, mx, o));
    if (lane == 0) red[warp] = mx;
    __syncthreads();
    if (tid < 32) {
        float m = (tid < 8) ? red[tid] : -1e30f;
        #pragma unroll
        for (int o = 4; o > 0; o >>= 1)
            m = fmaxf(m, __shfl_xor_sync(0xffffffffu, m, o));
        if (tid == 0) red[0] = m;
    }
    __syncthreads();
    mx = red[0];
    __syncthreads();

    float s = 0.0f;
    #pragma unroll
    for (int i = 0; i < 4; ++i) {
        v[i].x = __expf(v[i].x - mx);
        v[i].y = __expf(v[i].y - mx);
        v[i].z = __expf(v[i].z - mx);
        v[i].w = __expf(v[i].w - mx);
        s += v[i].x + v[i].y + v[i].z + v[i].w;
    }
    #pragma unroll
    for (int o = 16; o > 0; o >>= 1)
        s += __shfl_xor_sync(0xffffffffu, s, o);
    if (lane == 0) red[warp] = s;
    __syncthreads();
    if (tid < 32) {
        float t = (tid < 8) ? red[tid] : 0.0f;
        #pragma unroll
        for (int o = 4; o > 0; o >>= 1)
            t += __shfl_xor_sync(0xffffffffu, t, o);
        if (tid == 0) red[0] = t;
    }
    __syncthreads();
    float rs = 1.0f / red[0];

    #pragma unroll
    for (int i = 0; i < 4; ++i) {
        size_t base = row * (size_t)NNPIX + i * 1024 + tid * 4;
        float pv[4] = {v[i].x * rs, v[i].y * rs, v[i].z * rs, v[i].w * rs};
        __nv_bfloat16 h[4], l[4];
        #pragma unroll
        for (int q = 0; q < 4; ++q) bsplit(pv[q], h[q], l[q]);
        *(__nv_bfloat162*)(g_Ph + base)     = __nv_bfloat162(h[0], h[1]);
        *(__nv_bfloat162*)(g_Ph + base + 2) = __nv_bfloat162(h[2], h[3]);
        *(__nv_bfloat162*)(g_Pl + base)     = __nv_bfloat162(l[0], l[1]);
        *(__nv_bfloat162*)(g_Pl + base + 2) = __nv_bfloat162(l[2], l[3]);
    }
}

// ======================= launch ==============================================
extern "C" void kernel_launch(void* const* d_in, const int* in_sizes, int n_in,
                              void* d_out, int out_size) {
    const float* X     = (const float*)d_in[0];
    const float* w1    = (const float*)d_in[1];
    const float* b1    = (const float*)d_in[2];
    const float* w2    = (const float*)d_in[3];
    const float* b2    = (const float*)d_in[4];
    const float* w3    = (const float*)d_in[5];
    const float* b3    = (const float*)d_in[6];
    const float* alpha = (const float*)d_in[7];
    float* out = (float*)d_out;

    cudaFuncSetAttribute(gemm_mma<0>, cudaFuncAttributeMaxDynamicSharedMemorySize, GSMEM);
    cudaFuncSetAttribute(gemm_mma<1>, cudaFuncAttributeMaxDynamicSharedMemorySize, GSMEM);
    cudaFuncSetAttribute(gemm_mma<2>, cudaFuncAttributeMaxDynamicSharedMemorySize, GSMEM);
    cudaFuncSetAttribute(gemm_mma<3>, cudaFuncAttributeMaxDynamicSharedMemorySize, GSMEM);

    prep_weights<<<6912, 256>>>(w1, w2, w3);
    im2col_kernel<<<dim3(64, 8, 8), 256>>>(X);

    // conv1: M=pix (im2col rows), N=co (weight rows) -> feat1 [b][pix][co]
    gemm_mma<0><<<dim3(4, 32, 8), 256, GSMEM>>>(
        1, 0LL, KCONV, 9437184LL,     0, 0LL,       KCONV, 0LL,
        KCONV, 0, 1048576LL, 256, nullptr, b1);
    // conv2 -> feat2 [b][pix][co]
    gemm_mma<0><<<dim3(4, 32, 8), 256, GSMEM>>>(
        1, 0LL, KCONV, 9437184LL,     0, 589824LL,  KCONV, 0LL,
        KCONV, 1, 1048576LL, 256, nullptr, b2);
    // conv3: M=co, N=pix -> feat3 [b][co][pix]
    gemm_mma<1><<<dim3(64, 2, 8), 256, GSMEM>>>(
        0, 1179648LL, KCONV, 0LL,     1, 0LL,       KCONV, 9437184LL,
        KCONV, 2, 1048576LL, 4096, nullptr, b3);

    // logits: S[n][m] = sum_c feat1[n][c] * feat2[m][c]
    gemm_mma<2><<<dim3(64, 32, 8), 256, GSMEM>>>(
        2, 0LL, 256, 1048576LL,       3, 0LL,       256,   1048576LL,
        256, 0, 16777216LL, 4096, nullptr, nullptr);

    softmax_kernel<<<BB * NNPIX, 256>>>();

    // final: out[c][n] = alpha * sum_m D[c][m] * P[n][m]
    gemm_mma<3><<<dim3(64, 2, 8), 256, GSMEM>>>(
        4, 0LL, 4096, 1048576LL,      5, 0LL,       4096,  16777216LL,
        4096, 0, 1048576LL, 4096, out, alpha);
}

// round 16
// speedup vs baseline: 1.3072x; 1.0078x over previous
#include <cuda_runtime.h>
#include <cuda_bf16.h>
#include <cstdint>
#include <cstddef>

// Problem: X [8,256,64,64]; three 3x3 SAME convs 256->256; spatial attention.
#define BB 8
#define CC 256
#define HH 64
#define WW 64
#define NNPIX 4096
#define KCONV 2304            // 9 taps * 256 ci

// ======================= scratch (__device__, no allocs) =====================
__device__ __align__(128) float          g_M[134217728];                 // logits fp32 [b][n][m]
__device__ __align__(128) __nv_bfloat16  g_Ph[134217728];                // probs hi  [b][n][m]
__device__ __align__(128) __nv_bfloat16  g_Pl[134217728];                // probs lo
__device__ __align__(128) __nv_bfloat16  g_Xch[75497472];                // im2col hi [b][n][k]
__device__ __align__(128) __nv_bfloat16  g_Xcl[75497472];                // im2col lo
__device__ __align__(128) __nv_bfloat16  g_Ah[8388608], g_Al[8388608];   // feat1 [b][n][c]
__device__ __align__(128) __nv_bfloat16  g_Bh[8388608], g_Bl[8388608];   // feat2 [b][n][c]
__device__ __align__(128) __nv_bfloat16  g_Dh[8388608], g_Dl[8388608];   // feat3 [b][c][n]
__device__ __align__(128) __nv_bfloat16  g_Wh[1769472], g_Wl[1769472];   // [which][co][k]

// ======================= helpers =============================================
__device__ __forceinline__ uint32_t smem_u32(const void* p) {
    uint32_t a;
    asm("{ .reg .u64 t; cvta.to.shared.u64 t, %1; cvt.u32.u64 %0, t; }"
        : "=r"(a) : "l"(p));
    return a;
}
__device__ __forceinline__ void cp16(uint32_t dst, const void* src) {
    asm volatile("cp.async.cg.shared.global [%0], [%1], 16;" :: "r"(dst), "l"(src));
}
#define CP_COMMIT() asm volatile("cp.async.commit_group;" ::: "memory")
#define CP_WAIT(n)  asm volatile("cp.async.wait_group %0;" :: "n"(n) : "memory")

__device__ __forceinline__ void ldsm_x4(uint32_t* r, uint32_t a) {
    asm volatile("ldmatrix.sync.aligned.m8n8.x4.shared.b16 {%0,%1,%2,%3}, [%4];"
        : "=r"(r[0]), "=r"(r[1]), "=r"(r[2]), "=r"(r[3]) : "r"(a));
}
__device__ __forceinline__ void mma_bf16(float* c, const uint32_t* a, const uint32_t* b) {
    asm volatile("mma.sync.aligned.m16n8k16.row.col.f32.bf16.bf16.f32 "
        "{%0,%1,%2,%3}, {%4,%5,%6,%7}, {%8,%9}, {%0,%1,%2,%3};"
        : "+f"(c[0]), "+f"(c[1]), "+f"(c[2]), "+f"(c[3])
        : "r"(a[0]), "r"(a[1]), "r"(a[2]), "r"(a[3]), "r"(b[0]), "r"(b[1]));
}
__device__ __forceinline__ void bsplit(float v, __nv_bfloat16& h, __nv_bfloat16& l) {
    h = __float2bfloat16(v);
    l = __float2bfloat16(v - __bfloat162float(h));
}

// ======================= prep: weights -> [which][co][tap*256+ci] hi/lo ======
__global__ void prep_weights(const float* __restrict__ w1,
                             const float* __restrict__ w2,
                             const float* __restrict__ w3) {
    int idx = blockIdx.x * 256 + threadIdx.x;      // < 3*589824
    int which = idx / 589824;
    int r     = idx % 589824;
    int co    = r / KCONV;
    int k     = r % KCONV;
    int tap   = k / 256;
    int ci    = k % 256;
    const float* w = (which == 0) ? w1 : (which == 1) ? w2 : w3;
    float v = w[(co * 256 + ci) * 9 + tap];
    bsplit(v, g_Wh[idx], g_Wl[idx]);
}

// ======================= prep: im2col hi/lo bf16 [b][n][tap*256+ci] ==========
__global__ void im2col_kernel(const float* __restrict__ X) {
    __shared__ float Xs[32][3][65];
    int y  = blockIdx.x;
    int c0 = blockIdx.y * 32;
    int b  = blockIdx.z;
    int tid = threadIdx.x;

    for (int i = tid; i < 32 * 3 * 64; i += 256) {
        int ci  = i / 192;
        int rem = i % 192;
        int r   = rem / 64;
        int x   = rem % 64;
        int yy  = y + r - 1;
        float v = 0.0f;
        if (yy >= 0 && yy < HH)
            v = X[((size_t)(b * CC + c0 + ci)) * NNPIX + yy * WW + x];
        Xs[ci][r][x] = v;
    }
    __syncthreads();

    for (int t = 0; t < 9; ++t) {
        int dy = t / 3, dx = t % 3 - 1;
        for (int i = tid; i < 2048; i += 256) {
            int ci = i & 31;
            int x  = i >> 5;
            int px = x + dx;
            float v = (px >= 0 && px < WW) ? Xs[ci][dy][px] : 0.0f;
            size_t o = ((size_t)(b * NNPIX + y * WW + x)) * KCONV + t * 256 + c0 + ci;
            bsplit(v, g_Xch[o], g_Xcl[o]);
        }
    }
}

// ======================= operand selectors ===================================
__device__ __forceinline__ const __nv_bfloat16* sel_h(int s) {
    switch (s) {
        case 0: return g_Wh;  case 1: return g_Xch; case 2: return g_Ah;
        case 3: return g_Bh;  case 4: return g_Dh;  default: return g_Ph;
    }
}
__device__ __forceinline__ const __nv_bfloat16* sel_l(int s) {
    switch (s) {
        case 0: return g_Wl;  case 1: return g_Xcl; case 2: return g_Al;
        case 3: return g_Bl;  case 4: return g_Dl;  default: return g_Pl;
    }
}
__device__ __forceinline__ __nv_bfloat16* sel_oh(int s) {
    return (s == 0) ? g_Ah : (s == 1) ? g_Bh : g_Dh;
}
__device__ __forceinline__ __nv_bfloat16* sel_ol(int s) {
    return (s == 0) ? g_Al : (s == 1) ? g_Bl : g_Dl;
}

// ======================= unified bf16 mma.sync GEMM ==========================
// D[m][n] = sum_k Aop[m][k] * Bop[n][k]  (both operands K-major), 3-pass hi/lo.
// Block tile 128x64, BK=32, 8 warps (4x2 -> 32x32 warp tiles), cp.async x3
// stages, ONE __syncthreads per chunk, 2 CTAs/SM (smem 92KB/CTA).
// Mainloop: paired-j x4 B ldsm (MMA:LDSM = 3:1) + pass-major MMA ordering
// (same-acc reuse distance 8) to keep the tensor pipe issue-fed.
// MODE 0: feat epilogue  (+bias[col], bf16 hi/lo out)   conv1/conv2
// MODE 1: featD epilogue (+bias[row], bf16 hi/lo out)   conv3
// MODE 2: logits epilogue (fp32 -> g_M)
// MODE 3: final epilogue  (fp32 * alpha -> outf)
#define TILEA   10240           // 128 rows * 80B (32 bf16 + 16B pad)
#define TILEBT  5120            // 64 rows * 80B
#define STAGEB  (2 * TILEA + 2 * TILEBT)   // 30720
#define NSTAGE  3
#define GSMEM   (NSTAGE * STAGEB)          // 92160

template <int MODE>
__global__ void __launch_bounds__(256, 2)
gemm_mma(int asel, long long a_off, long a_rs, long long a_bs,
         int bsel, long long b_off, long b_rs, long long b_bs,
         int Ktot, int osel, long long o_bs, int ldo,
         float* outf, const float* __restrict__ bias)
{
    extern __shared__ char smem[];
    uint32_t sb = smem_u32(smem);
    int tid  = threadIdx.x;
    int wid  = tid >> 5, lane = tid & 31;
    int g    = lane >> 2, tig = lane & 3;
    int wm   = (wid >> 1) * 32;       // warp m-offset (4 rows of warps)
    int wn   = (wid & 1) * 32;        // warp n-offset (2 cols)

    int bn0 = blockIdx.x * 64;
    int bm0 = blockIdx.y * 128;
    int b   = blockIdx.z;

    const __nv_bfloat16* pAh = sel_h(asel) + a_off + (size_t)b * a_bs + (size_t)bm0 * a_rs;
    const __nv_bfloat16* pAl = sel_l(asel) + a_off + (size_t)b * a_bs + (size_t)bm0 * a_rs;
    const __nv_bfloat16* pBh = sel_h(bsel) + b_off + (size_t)b * b_bs + (size_t)bn0 * b_rs;
    const __nv_bfloat16* pBl = sel_l(bsel) + b_off + (size_t)b * b_bs + (size_t)bn0 * b_rs;

    float acc[2][4][4] = {};
    const int NC = Ktot >> 5;

    // ---- stage loader: A 2x512 chunks, B 2x256 chunks (16B each) ----
    auto stage_load = [&](int s, int kc) {
        uint32_t base = sb + s * STAGEB;
        #pragma unroll
        for (int i = 0; i < 2; ++i) {
            int u   = tid + i * 256;          // 0..511
            int row = u >> 2;
            int ch  = u & 3;
            size_t ka = (size_t)row * a_rs + kc + ch * 8;
            uint32_t d = base + row * 80 + ch * 16;
            cp16(d,         pAh + ka);
            cp16(d + TILEA, pAl + ka);
        }
        {
            int row = tid >> 2;               // 0..63
            int ch  = tid & 3;
            size_t kb = (size_t)row * b_rs + kc + ch * 8;
            uint32_t d = base + 2 * TILEA + row * 80 + ch * 16;
            cp16(d,          pBh + kb);
            cp16(d + TILEBT, pBl + kb);
        }
    };

    // prefetch two stages
    stage_load(0, 0);
    CP_COMMIT();
    if (NC > 1) { stage_load(1, 32); CP_COMMIT(); }

    // A ldsm: m16k16 frags. B ldsm: paired-j x4 (two n8k16 frags per x4).
    uint32_t arow = (wm + (lane & 15)) * 80 + ((lane >> 4) * 16);
    uint32_t brow = (wn + ((lane >> 4) << 3) + (lane & 7)) * 80 + (((lane >> 3) & 1) << 4);

    int slot = 0;
    for (int c = 0; c < NC; ++c) {
        if (c + 1 < NC) { CP_WAIT(1); } else { CP_WAIT(0); }
        __syncthreads();                       // stage c ready; all warps done with c-1

        if (c + 2 < NC) {                      // refill slot holding stage c-1
            int ns = slot + 2; if (ns >= NSTAGE) ns -= NSTAGE;
            stage_load(ns, (c + 2) * 32);
            CP_COMMIT();
        }

        uint32_t Ab = sb + slot * STAGEB;
        uint32_t Bb = Ab + 2 * TILEA;

        #pragma unroll
        for (int ks = 0; ks < 2; ++ks) {
            // ---- load ALL fragments for this k16 step ----
            uint32_t bh[2][4], bl[2][4], ah[2][4], al[2][4];
            #pragma unroll
            for (int jp = 0; jp < 2; ++jp) {
                uint32_t ra = Bb + brow + jp * (16 * 80) + ks * 32;
                ldsm_x4(bh[jp], ra);
                ldsm_x4(bl[jp], ra + TILEBT);
            }
            #pragma unroll
            for (int i = 0; i < 2; ++i) {
                uint32_t ra = Ab + arow + i * (16 * 80) + ks * 32;
                ldsm_x4(ah[i], ra);
                ldsm_x4(al[i], ra + TILEA);
            }
            // ---- pass-major MMA: 8 independent accs per pass ----
            #pragma unroll
            for (int i = 0; i < 2; ++i)
                #pragma unroll
                for (int j = 0; j < 4; ++j)
                    mma_bf16(acc[i][j], ah[i], &bh[j >> 1][(j & 1) * 2]);   // hi*hi
            #pragma unroll
            for (int i = 0; i < 2; ++i)
                #pragma unroll
                for (int j = 0; j < 4; ++j)
                    mma_bf16(acc[i][j], ah[i], &bl[j >> 1][(j & 1) * 2]);   // hi*lo
            #pragma unroll
            for (int i = 0; i < 2; ++i)
                #pragma unroll
                for (int j = 0; j < 4; ++j)
                    mma_bf16(acc[i][j], al[i], &bh[j >> 1][(j & 1) * 2]);   // lo*hi
        }

        if (++slot == NSTAGE) slot = 0;
    }

    // ---- epilogue ----
    const float alpha = (MODE == 3) ? bias[0] : 1.0f;
    __nv_bfloat16* oh = (MODE <= 1) ? sel_oh(osel) : (__nv_bfloat16*)0;
    __nv_bfloat16* ol = (MODE <= 1) ? sel_ol(osel) : (__nv_bfloat16*)0;
    float* ofp = (MODE == 2) ? g_M : outf;
    size_t ob = (size_t)b * o_bs;

    #pragma unroll
    for (int i = 0; i < 2; ++i) {
        int row = bm0 + wm + i * 16 + g;
        float br0 = 0.0f, br1 = 0.0f;
        if (MODE == 1) { br0 = bias[row]; br1 = bias[row + 8]; }
        #pragma unroll
        for (int j = 0; j < 4; ++j) {
            int col = bn0 + wn + j * 8 + tig * 2;
            float v00 = acc[i][j][0], v01 = acc[i][j][1];
            float v10 = acc[i][j][2], v11 = acc[i][j][3];
            if (MODE == 0) {
                float bc0 = bias[col], bc1 = bias[col + 1];
                v00 += bc0; v01 += bc1; v10 += bc0; v11 += bc1;
            } else if (MODE == 1) {
                v00 += br0; v01 += br0; v10 += br1; v11 += br1;
            }
            size_t o0 = ob + (size_t)row * ldo + col;
            size_t o1 = o0 + (size_t)8 * ldo;
            if (MODE >= 2) {
                *(float2*)(ofp + o0) = make_float2(alpha * v00, alpha * v01);
                *(float2*)(ofp + o1) = make_float2(alpha * v10, alpha * v11);
            } else {
                __nv_bfloat16 h0, l0, h1, l1;
                bsplit(v00, h0, l0); bsplit(v01, h1, l1);
                *(__nv_bfloat162*)(oh + o0) = __nv_bfloat162(h0, h1);
                *(__nv_bfloat162*)(ol + o0) = __nv_bfloat162(l0, l1);
                bsplit(v10, h0, l0); bsplit(v11, h1, l1);
                *(__nv_bfloat162*)(oh + o1) = __nv_bfloat162(h0, h1);
                *(__nv_bfloat162*)(ol + o1) = __nv_bfloat162(l0, l1);
            }
        }
    }
}

// ======================= softmax: g_M row -> Ph/Pl bf16 ======================
__global__ void softmax_kernel() {
    __shared__ float red[32];
    size_t row = blockIdx.x;
    const float4* p = (const float4*)(g_M + row * (size_t)NNPIX);

    int tid  = threadIdx.x;
    int lane = tid & 31;
    int warp = tid >> 5;

    float4 v[4];
    #pragma unroll
    for (int i = 0; i < 4; ++i) v[i] = p[i * 256 + tid];

    float mx = -1e30f;
    #pragma unroll
    for (int i = 0; i < 4; ++i)
        mx = fmaxf(mx, fmaxf(fmaxf(v[i].x, v[i].y), fmaxf(v[i].z, v[i].w)));
    #pragma unroll
    for (int o = 16; o > 0; o >>= 1)
        mx = fmaxf(mx, __shfl_xor_sync(0xffffffffu, mx, o));
    if (lane == 0) red[warp] = mx;
    __syncthreads();
    if (tid < 32) {
        float m = (tid < 8) ? red[tid] : -1e30f;
        #pragma unroll
        for (int o = 4; o > 0; o >>= 1)
            m = fmaxf(m, __shfl_xor_sync(0xffffffffu, m, o));
        if (tid == 0) red[0] = m;
    }
    __syncthreads();
    mx = red[0];
    __syncthreads();

    float s = 0.0f;
    #pragma unroll
    for (int i = 0; i < 4; ++i) {
        v[i].x = __expf(v[i].x - mx);
        v[i].y = __expf(v[i].y - mx);
        v[i].z = __expf(v[i].z - mx);
        v[i].w = __expf(v[i].w - mx);
        s += v[i].x + v[i].y + v[i].z + v[i].w;
    }
    #pragma unroll
    for (int o = 16; o > 0; o >>= 1)
        s += __shfl_xor_sync(0xffffffffu, s, o);
    if (lane == 0) red[warp] = s;
    __syncthreads();
    if (tid < 32) {
        float t = (tid < 8) ? red[tid] : 0.0f;
        #pragma unroll
        for (int o = 4; o > 0; o >>= 1)
            t += __shfl_xor_sync(0xffffffffu, t, o);
        if (tid == 0) red[0] = t;
    }
    __syncthreads();
    float rs = 1.0f / red[0];

    #pragma unroll
    for (int i = 0; i < 4; ++i) {
        size_t base = row * (size_t)NNPIX + i * 1024 + tid * 4;
        float pv[4] = {v[i].x * rs, v[i].y * rs, v[i].z * rs, v[i].w * rs};
        __nv_bfloat16 h[4], l[4];
        #pragma unroll
        for (int q = 0; q < 4; ++q) bsplit(pv[q], h[q], l[q]);
        *(__nv_bfloat162*)(g_Ph + base)     = __nv_bfloat162(h[0], h[1]);
        *(__nv_bfloat162*)(g_Ph + base + 2) = __nv_bfloat162(h[2], h[3]);
        *(__nv_bfloat162*)(g_Pl + base)     = __nv_bfloat162(l[0], l[1]);
        *(__nv_bfloat162*)(g_Pl + base + 2) = __nv_bfloat162(l[2], l[3]);
    }
}

// ======================= launch ==============================================
extern "C" void kernel_launch(void* const* d_in, const int* in_sizes, int n_in,
                              void* d_out, int out_size) {
    const float* X     = (const float*)d_in[0];
    const float* w1    = (const float*)d_in[1];
    const float* b1    = (const float*)d_in[2];
    const float* w2    = (const float*)d_in[3];
    const float* b2    = (const float*)d_in[4];
    const float* w3    = (const float*)d_in[5];
    const float* b3    = (const float*)d_in[6];
    const float* alpha = (const float*)d_in[7];
    float* out = (float*)d_out;

    cudaFuncSetAttribute(gemm_mma<0>, cudaFuncAttributeMaxDynamicSharedMemorySize, GSMEM);
    cudaFuncSetAttribute(gemm_mma<1>, cudaFuncAttributeMaxDynamicSharedMemorySize, GSMEM);
    cudaFuncSetAttribute(gemm_mma<2>, cudaFuncAttributeMaxDynamicSharedMemorySize, GSMEM);
    cudaFuncSetAttribute(gemm_mma<3>, cudaFuncAttributeMaxDynamicSharedMemorySize, GSMEM);

    prep_weights<<<6912, 256>>>(w1, w2, w3);
    im2col_kernel<<<dim3(64, 8, 8), 256>>>(X);

    // conv1: M=pix (im2col rows), N=co (weight rows) -> feat1 [b][pix][co]
    gemm_mma<0><<<dim3(4, 32, 8), 256, GSMEM>>>(
        1, 0LL, KCONV, 9437184LL,     0, 0LL,       KCONV, 0LL,
        KCONV, 0, 1048576LL, 256, nullptr, b1);
    // conv2 -> feat2 [b][pix][co]
    gemm_mma<0><<<dim3(4, 32, 8), 256, GSMEM>>>(
        1, 0LL, KCONV, 9437184LL,     0, 589824LL,  KCONV, 0LL,
        KCONV, 1, 1048576LL, 256, nullptr, b2);
    // conv3: M=co, N=pix -> feat3 [b][co][pix]
    gemm_mma<1><<<dim3(64, 2, 8), 256, GSMEM>>>(
        0, 1179648LL, KCONV, 0LL,     1, 0LL,       KCONV, 9437184LL,
        KCONV, 2, 1048576LL, 4096, nullptr, b3);

    // logits: S[n][m] = sum_c feat1[n][c] * feat2[m][c]
    gemm_mma<2><<<dim3(64, 32, 8), 256, GSMEM>>>(
        2, 0LL, 256, 1048576LL,       3, 0LL,       256,   1048576LL,
        256, 0, 16777216LL, 4096, nullptr, nullptr);

    softmax_kernel<<<BB * NNPIX, 256>>>();

    // final: out[c][n] = alpha * sum_m D[c][m] * P[n][m]
    gemm_mma<3><<<dim3(64, 2, 8), 256, GSMEM>>>(
        4, 0LL, 4096, 1048576LL,      5, 0LL,       4096,  16777216LL,
        4096, 0, 1048576LL, 4096, out, alpha);
}

// round 17
// speedup vs baseline: 1.4083x; 1.0773x over previous
#include <cuda_runtime.h>
#include <cuda_bf16.h>
#include <cstdint>
#include <cstddef>

// Problem: X [8,256,64,64]; three 3x3 SAME convs 256->256; spatial attention.
#define BB 8
#define CC 256
#define HH 64
#define WW 64
#define NNPIX 4096
#define KCONV 2304            // 9 taps * 256 ci

// ======================= scratch (__device__, no allocs) =====================
__device__ __align__(128) float          g_M[134217728];                 // logits/probs fp32 [b][n][m]
__device__ __align__(128) __nv_bfloat16  g_Xch[75497472];                // im2col hi [b][n][k]
__device__ __align__(128) __nv_bfloat16  g_Xcl[75497472];                // im2col lo
__device__ __align__(128) __nv_bfloat16  g_Ah[8388608], g_Al[8388608];   // feat1 [b][n][c]
__device__ __align__(128) __nv_bfloat16  g_Bh[8388608], g_Bl[8388608];   // feat2 [b][n][c]
__device__ __align__(128) float          g_Df[8388608];                  // feat3 tf32 [b][c][n]
__device__ __align__(128) __nv_bfloat16  g_Wh[1769472], g_Wl[1769472];   // [which][co][k]

// ======================= helpers =============================================
__device__ __forceinline__ uint32_t smem_u32(const void* p) {
    uint32_t a;
    asm("{ .reg .u64 t; cvta.to.shared.u64 t, %1; cvt.u32.u64 %0, t; }"
        : "=r"(a) : "l"(p));
    return a;
}
__device__ __forceinline__ void cp16(uint32_t dst, const void* src) {
    asm volatile("cp.async.cg.shared.global [%0], [%1], 16;" :: "r"(dst), "l"(src));
}
#define CP_COMMIT() asm volatile("cp.async.commit_group;" ::: "memory")
#define CP_WAIT(n)  asm volatile("cp.async.wait_group %0;" :: "n"(n) : "memory")

__device__ __forceinline__ void ldsm_x4(uint32_t* r, uint32_t a) {
    asm volatile("ldmatrix.sync.aligned.m8n8.x4.shared.b16 {%0,%1,%2,%3}, [%4];"
        : "=r"(r[0]), "=r"(r[1]), "=r"(r[2]), "=r"(r[3]) : "r"(a));
}
__device__ __forceinline__ void mma_bf16(float* c, const uint32_t* a, const uint32_t* b) {
    asm volatile("mma.sync.aligned.m16n8k16.row.col.f32.bf16.bf16.f32 "
        "{%0,%1,%2,%3}, {%4,%5,%6,%7}, {%8,%9}, {%0,%1,%2,%3};"
        : "+f"(c[0]), "+f"(c[1]), "+f"(c[2]), "+f"(c[3])
        : "r"(a[0]), "r"(a[1]), "r"(a[2]), "r"(a[3]), "r"(b[0]), "r"(b[1]));
}
__device__ __forceinline__ void mma_tf32(float* c, const uint32_t* a, const uint32_t* b) {
    asm volatile("mma.sync.aligned.m16n8k8.row.col.f32.tf32.tf32.f32 "
        "{%0,%1,%2,%3}, {%4,%5,%6,%7}, {%8,%9}, {%0,%1,%2,%3};"
        : "+f"(c[0]), "+f"(c[1]), "+f"(c[2]), "+f"(c[3])
        : "r"(a[0]), "r"(a[1]), "r"(a[2]), "r"(a[3]), "r"(b[0]), "r"(b[1]));
}
__device__ __forceinline__ void bsplit(float v, __nv_bfloat16& h, __nv_bfloat16& l) {
    h = __float2bfloat16(v);
    l = __float2bfloat16(v - __bfloat162float(h));
}
__device__ __forceinline__ float to_tf32(float v) {
    uint32_t r;
    asm("cvt.rna.tf32.f32 %0, %1;" : "=r"(r) : "f"(v));
    return __uint_as_float(r);
}

// ======================= prep: weights -> [which][co][tap*256+ci] hi/lo ======
__global__ void prep_weights(const float* __restrict__ w1,
                             const float* __restrict__ w2,
                             const float* __restrict__ w3) {
    int idx = blockIdx.x * 256 + threadIdx.x;      // < 3*589824
    int which = idx / 589824;
    int r     = idx % 589824;
    int co    = r / KCONV;
    int k     = r % KCONV;
    int tap   = k / 256;
    int ci    = k % 256;
    const float* w = (which == 0) ? w1 : (which == 1) ? w2 : w3;
    float v = w[(co * 256 + ci) * 9 + tap];
    bsplit(v, g_Wh[idx], g_Wl[idx]);
}

// ======================= prep: im2col hi/lo bf16 [b][n][tap*256+ci] ==========
__global__ void im2col_kernel(const float* __restrict__ X) {
    __shared__ float Xs[32][3][65];
    int y  = blockIdx.x;
    int c0 = blockIdx.y * 32;
    int b  = blockIdx.z;
    int tid = threadIdx.x;

    for (int i = tid; i < 32 * 3 * 64; i += 256) {
        int ci  = i / 192;
        int rem = i % 192;
        int r   = rem / 64;
        int x   = rem % 64;
        int yy  = y + r - 1;
        float v = 0.0f;
        if (yy >= 0 && yy < HH)
            v = X[((size_t)(b * CC + c0 + ci)) * NNPIX + yy * WW + x];
        Xs[ci][r][x] = v;
    }
    __syncthreads();

    for (int t = 0; t < 9; ++t) {
        int dy = t / 3, dx = t % 3 - 1;
        for (int i = tid; i < 2048; i += 256) {
            int ci = i & 31;
            int x  = i >> 5;
            int px = x + dx;
            float v = (px >= 0 && px < WW) ? Xs[ci][dy][px] : 0.0f;
            size_t o = ((size_t)(b * NNPIX + y * WW + x)) * KCONV + t * 256 + c0 + ci;
            bsplit(v, g_Xch[o], g_Xcl[o]);
        }
    }
}

// ======================= operand selectors ===================================
__device__ __forceinline__ const __nv_bfloat16* sel_h(int s) {
    switch (s) {
        case 0: return g_Wh;  case 1: return g_Xch; case 2: return g_Ah;
        default: return g_Bh;
    }
}
__device__ __forceinline__ const __nv_bfloat16* sel_l(int s) {
    switch (s) {
        case 0: return g_Wl;  case 1: return g_Xcl; case 2: return g_Al;
        default: return g_Bl;
    }
}
__device__ __forceinline__ __nv_bfloat16* sel_oh(int s) { return (s == 0) ? g_Ah : g_Bh; }
__device__ __forceinline__ __nv_bfloat16* sel_ol(int s) { return (s == 0) ? g_Al : g_Bl; }

// ======================= unified bf16 mma.sync GEMM ==========================
// D[m][n] = sum_k Aop[m][k] * Bop[n][k]  (both operands K-major), 3-pass hi/lo.
// Block tile 128x64, BK=32, 8 warps (4x2 -> 32x32 warp tiles), cp.async x3
// stages, ONE __syncthreads per chunk, 2 CTAs/SM (smem 92KB/CTA).
// MODE 0: feat epilogue  (+bias[col], bf16 hi/lo out)   conv1/conv2
// MODE 1: featD epilogue (+bias[row], tf32 fp32 out)    conv3
// MODE 2: logits epilogue (fp32 -> g_M)
#define TILEA   10240           // 128 rows * 80B (32 bf16 + 16B pad)
#define TILEBT  5120            // 64 rows * 80B
#define STAGEB  (2 * TILEA + 2 * TILEBT)   // 30720
#define NSTAGE  3
#define GSMEM   (NSTAGE * STAGEB)          // 92160

template <int MODE>
__global__ void __launch_bounds__(256, 2)
gemm_mma(int asel, long long a_off, long a_rs, long long a_bs,
         int bsel, long long b_off, long b_rs, long long b_bs,
         int Ktot, int osel, long long o_bs, int ldo,
         const float* __restrict__ bias)
{
    extern __shared__ char smem[];
    uint32_t sb = smem_u32(smem);
    int tid  = threadIdx.x;
    int wid  = tid >> 5, lane = tid & 31;
    int g    = lane >> 2, tig = lane & 3;
    int wm   = (wid >> 1) * 32;       // warp m-offset (4 rows of warps)
    int wn   = (wid & 1) * 32;        // warp n-offset (2 cols)

    int bn0 = blockIdx.x * 64;
    int bm0 = blockIdx.y * 128;
    int b   = blockIdx.z;

    const __nv_bfloat16* pAh = sel_h(asel) + a_off + (size_t)b * a_bs + (size_t)bm0 * a_rs;
    const __nv_bfloat16* pAl = sel_l(asel) + a_off + (size_t)b * a_bs + (size_t)bm0 * a_rs;
    const __nv_bfloat16* pBh = sel_h(bsel) + b_off + (size_t)b * b_bs + (size_t)bn0 * b_rs;
    const __nv_bfloat16* pBl = sel_l(bsel) + b_off + (size_t)b * b_bs + (size_t)bn0 * b_rs;

    float acc[2][4][4] = {};
    const int NC = Ktot >> 5;

    auto stage_load = [&](int s, int kc) {
        uint32_t base = sb + s * STAGEB;
        #pragma unroll
        for (int i = 0; i < 2; ++i) {
            int u   = tid + i * 256;          // 0..511
            int row = u >> 2;
            int ch  = u & 3;
            size_t ka = (size_t)row * a_rs + kc + ch * 8;
            uint32_t d = base + row * 80 + ch * 16;
            cp16(d,         pAh + ka);
            cp16(d + TILEA, pAl + ka);
        }
        {
            int row = tid >> 2;               // 0..63
            int ch  = tid & 3;
            size_t kb = (size_t)row * b_rs + kc + ch * 8;
            uint32_t d = base + 2 * TILEA + row * 80 + ch * 16;
            cp16(d,          pBh + kb);
            cp16(d + TILEBT, pBl + kb);
        }
    };

    stage_load(0, 0);
    CP_COMMIT();
    if (NC > 1) { stage_load(1, 32); CP_COMMIT(); }

    uint32_t arow = (wm + (lane & 15)) * 80 + ((lane >> 4) * 16);
    uint32_t brow = (wn + ((lane >> 4) << 3) + (lane & 7)) * 80 + (((lane >> 3) & 1) << 4);

    int slot = 0;
    for (int c = 0; c < NC; ++c) {
        if (c + 1 < NC) { CP_WAIT(1); } else { CP_WAIT(0); }
        __syncthreads();

        if (c + 2 < NC) {
            int ns = slot + 2; if (ns >= NSTAGE) ns -= NSTAGE;
            stage_load(ns, (c + 2) * 32);
            CP_COMMIT();
        }

        uint32_t Ab = sb + slot * STAGEB;
        uint32_t Bb = Ab + 2 * TILEA;

        #pragma unroll
        for (int ks = 0; ks < 2; ++ks) {
            uint32_t bh[2][4], bl[2][4], ah[2][4], al[2][4];
            #pragma unroll
            for (int jp = 0; jp < 2; ++jp) {
                uint32_t ra = Bb + brow + jp * (16 * 80) + ks * 32;
                ldsm_x4(bh[jp], ra);
                ldsm_x4(bl[jp], ra + TILEBT);
            }
            #pragma unroll
            for (int i = 0; i < 2; ++i) {
                uint32_t ra = Ab + arow + i * (16 * 80) + ks * 32;
                ldsm_x4(ah[i], ra);
                ldsm_x4(al[i], ra + TILEA);
            }
            #pragma unroll
            for (int i = 0; i < 2; ++i)
                #pragma unroll
                for (int j = 0; j < 4; ++j)
                    mma_bf16(acc[i][j], ah[i], &bh[j >> 1][(j & 1) * 2]);   // hi*hi
            #pragma unroll
            for (int i = 0; i < 2; ++i)
                #pragma unroll
                for (int j = 0; j < 4; ++j)
                    mma_bf16(acc[i][j], ah[i], &bl[j >> 1][(j & 1) * 2]);   // hi*lo
            #pragma unroll
            for (int i = 0; i < 2; ++i)
                #pragma unroll
                for (int j = 0; j < 4; ++j)
                    mma_bf16(acc[i][j], al[i], &bh[j >> 1][(j & 1) * 2]);   // lo*hi
        }

        if (++slot == NSTAGE) slot = 0;
    }

    // ---- epilogue ----
    __nv_bfloat16* oh = (MODE == 0) ? sel_oh(osel) : (__nv_bfloat16*)0;
    __nv_bfloat16* ol = (MODE == 0) ? sel_ol(osel) : (__nv_bfloat16*)0;
    size_t ob = (size_t)b * o_bs;

    #pragma unroll
    for (int i = 0; i < 2; ++i) {
        int row = bm0 + wm + i * 16 + g;
        float br0 = 0.0f, br1 = 0.0f;
        if (MODE == 1) { br0 = bias[row]; br1 = bias[row + 8]; }
        #pragma unroll
        for (int j = 0; j < 4; ++j) {
            int col = bn0 + wn + j * 8 + tig * 2;
            float v00 = acc[i][j][0], v01 = acc[i][j][1];
            float v10 = acc[i][j][2], v11 = acc[i][j][3];
            size_t o0 = ob + (size_t)row * ldo + col;
            size_t o1 = o0 + (size_t)8 * ldo;
            if (MODE == 2) {
                *(float2*)(g_M + o0) = make_float2(v00, v01);
                *(float2*)(g_M + o1) = make_float2(v10, v11);
            } else if (MODE == 1) {
                *(float2*)(g_Df + o0) = make_float2(to_tf32(v00 + br0), to_tf32(v01 + br0));
                *(float2*)(g_Df + o1) = make_float2(to_tf32(v10 + br1), to_tf32(v11 + br1));
            } else {
                float bc0 = bias[col], bc1 = bias[col + 1];
                v00 += bc0; v01 += bc1; v10 += bc0; v11 += bc1;
                __nv_bfloat16 h0, l0, h1, l1;
                bsplit(v00, h0, l0); bsplit(v01, h1, l1);
                *(__nv_bfloat162*)(oh + o0) = __nv_bfloat162(h0, h1);
                *(__nv_bfloat162*)(ol + o0) = __nv_bfloat162(l0, l1);
                bsplit(v10, h0, l0); bsplit(v11, h1, l1);
                *(__nv_bfloat162*)(oh + o1) = __nv_bfloat162(h0, h1);
                *(__nv_bfloat162*)(ol + o1) = __nv_bfloat162(l0, l1);
            }
        }
    }
}

// ======================= tf32 final GEMM =====================================
// out[c][n] = alpha * sum_m Df[c][m] * P[n][m], single-pass tf32 m16n8k8.
// Block tile 128(c) x 64(n), BK=32 fp32, pitch 144B, 3 stages, 2 CTAs/SM.
// ldmatrix trick: m16xk8 fp32 tile == m16xk16 bf16 tile in bytes; the b16
// x4/x2 lane->address formulas produce exactly the tf32 fragment layout.
#define TF_TILEA 18432          // 128 rows * 144B (32 fp32 + 16B pad)
#define TF_TILEB 9216           // 64 rows * 144B
#define TF_STAGE (TF_TILEA + TF_TILEB)     // 27648
#define TF_SMEM  (NSTAGE * TF_STAGE)       // 82944

__global__ void __launch_bounds__(256, 2)
gemm_tf32_final(float* __restrict__ outf, const float* __restrict__ alpha_p)
{
    extern __shared__ char smem[];
    uint32_t sb = smem_u32(smem);
    int tid  = threadIdx.x;
    int wid  = tid >> 5, lane = tid & 31;
    int g    = lane >> 2, tig = lane & 3;
    int wm   = (wid >> 1) * 32;
    int wn   = (wid & 1) * 32;

    int bn0 = blockIdx.x * 64;       // n tile
    int bm0 = blockIdx.y * 128;      // c tile
    int b   = blockIdx.z;

    const float* pA = g_Df + (size_t)b * 1048576 + (size_t)bm0 * NNPIX;
    const float* pB = g_M  + (size_t)b * 16777216 + (size_t)bn0 * NNPIX;

    float acc[2][4][4] = {};
    const int NC = NNPIX / 32;       // 128 chunks

    auto stage_load = [&](int s, int kc) {
        uint32_t base = sb + s * TF_STAGE;
        #pragma unroll
        for (int i = 0; i < 4; ++i) {
            int u   = tid + i * 256;          // 0..1023
            int row = u >> 3;
            int ch  = u & 7;
            cp16(base + row * 144 + ch * 16, pA + (size_t)row * NNPIX + kc + ch * 4);
        }
        #pragma unroll
        for (int i = 0; i < 2; ++i) {
            int u   = tid + i * 256;          // 0..511
            int row = u >> 3;                 // 0..63
            int ch  = u & 7;
            cp16(base + TF_TILEA + row * 144 + ch * 16,
                 pB + (size_t)row * NNPIX + kc + ch * 4);
        }
    };

    stage_load(0, 0);
    CP_COMMIT();
    stage_load(1, 32);
    CP_COMMIT();

    uint32_t arow = (wm + (lane & 15)) * 144 + ((lane >> 4) << 4);
    uint32_t brow = (wn + ((lane >> 4) << 3) + (lane & 7)) * 144 + (((lane >> 3) & 1) << 4);

    int slot = 0;
    for (int c = 0; c < NC; ++c) {
        if (c + 1 < NC) { CP_WAIT(1); } else { CP_WAIT(0); }
        __syncthreads();

        if (c + 2 < NC) {
            int ns = slot + 2; if (ns >= NSTAGE) ns -= NSTAGE;
            stage_load(ns, (c + 2) * 32);
            CP_COMMIT();
        }

        uint32_t Ab = sb + slot * TF_STAGE;
        uint32_t Bb = Ab + TF_TILEA;

        #pragma unroll
        for (int ks = 0; ks < 4; ++ks) {          // 4 k8 steps, 32B apart
            uint32_t bf[2][4], af[2][4];
            #pragma unroll
            for (int jp = 0; jp < 2; ++jp)
                ldsm_x4(bf[jp], Bb + brow + jp * (16 * 144) + ks * 32);
            #pragma unroll
            for (int i = 0; i < 2; ++i)
                ldsm_x4(af[i], Ab + arow + i * (16 * 144) + ks * 32);
            #pragma unroll
            for (int i = 0; i < 2; ++i)
                #pragma unroll
                for (int j = 0; j < 4; ++j)
                    mma_tf32(acc[i][j], af[i], &bf[j >> 1][(j & 1) * 2]);
        }

        if (++slot == NSTAGE) slot = 0;
    }

    const float alpha = alpha_p[0];
    size_t ob = (size_t)b * 1048576;
    #pragma unroll
    for (int i = 0; i < 2; ++i) {
        int row = bm0 + wm + i * 16 + g;          // c
        #pragma unroll
        for (int j = 0; j < 4; ++j) {
            int col = bn0 + wn + j * 8 + tig * 2; // n
            size_t o0 = ob + (size_t)row * NNPIX + col;
            size_t o1 = o0 + (size_t)8 * NNPIX;
            *(float2*)(outf + o0) = make_float2(alpha * acc[i][j][0], alpha * acc[i][j][1]);
            *(float2*)(outf + o1) = make_float2(alpha * acc[i][j][2], alpha * acc[i][j][3]);
        }
    }
}

// ======================= softmax: g_M row -> probs (tf32, in place) ==========
__global__ void softmax_kernel() {
    __shared__ float red[32];
    size_t row = blockIdx.x;
    float4* p = (float4*)(g_M + row * (size_t)NNPIX);

    int tid  = threadIdx.x;
    int lane = tid & 31;
    int warp = tid >> 5;

    float4 v[4];
    #pragma unroll
    for (int i = 0; i < 4; ++i) v[i] = p[i * 256 + tid];

    float mx = -1e30f;
    #pragma unroll
    for (int i = 0; i < 4; ++i)
        mx = fmaxf(mx, fmaxf(fmaxf(v[i].x, v[i].y), fmaxf(v[i].z, v[i].w)));
    #pragma unroll
    for (int o = 16; o > 0; o >>= 1)
        mx = fmaxf(mx, __shfl_xor_sync(0xffffffffu, mx, o));
    if (lane == 0) red[warp] = mx;
    __syncthreads();
    if (tid < 32) {
        float m = (tid < 8) ? red[tid] : -1e30f;
        #pragma unroll
        for (int o = 4; o > 0; o >>= 1)
            m = fmaxf(m, __shfl_xor_sync(0xffffffffu, m, o));
        if (tid == 0) red[0] = m;
    }
    __syncthreads();
    mx = red[0];
    __syncthreads();

    float s = 0.0f;
    #pragma unroll
    for (int i = 0; i < 4; ++i) {
        v[i].x = __expf(v[i].x - mx);
        v[i].y = __expf(v[i].y - mx);
        v[i].z = __expf(v[i].z - mx);
        v[i].w = __expf(v[i].w - mx);
        s += v[i].x + v[i].y + v[i].z + v[i].w;
    }
    #pragma unroll
    for (int o = 16; o > 0; o >>= 1)
        s += __shfl_xor_sync(0xffffffffu, s, o);
    if (lane == 0) red[warp] = s;
    __syncthreads();
    if (tid < 32) {
        float t = (tid < 8) ? red[tid] : 0.0f;
        #pragma unroll
        for (int o = 4; o > 0; o >>= 1)
            t += __shfl_xor_sync(0xffffffffu, t, o);
        if (tid == 0) red[0] = t;
    }
    __syncthreads();
    float rs = 1.0f / red[0];

    #pragma unroll
    for (int i = 0; i < 4; ++i) {
        float4 w;
        w.x = to_tf32(v[i].x * rs);
        w.y = to_tf32(v[i].y * rs);
        w.z = to_tf32(v[i].z * rs);
        w.w = to_tf32(v[i].w * rs);
        p[i * 256 + tid] = w;
    }
}

// ======================= launch ==============================================
extern "C" void kernel_launch(void* const* d_in, const int* in_sizes, int n_in,
                              void* d_out, int out_size) {
    const float* X     = (const float*)d_in[0];
    const float* w1    = (const float*)d_in[1];
    const float* b1    = (const float*)d_in[2];
    const float* w2    = (const float*)d_in[3];
    const float* b2    = (const float*)d_in[4];
    const float* w3    = (const float*)d_in[5];
    const float* b3    = (const float*)d_in[6];
    const float* alpha = (const float*)d_in[7];
    float* out = (float*)d_out;

    cudaFuncSetAttribute(gemm_mma<0>, cudaFuncAttributeMaxDynamicSharedMemorySize, GSMEM);
    cudaFuncSetAttribute(gemm_mma<1>, cudaFuncAttributeMaxDynamicSharedMemorySize, GSMEM);
    cudaFuncSetAttribute(gemm_mma<2>, cudaFuncAttributeMaxDynamicSharedMemorySize, GSMEM);
    cudaFuncSetAttribute(gemm_tf32_final, cudaFuncAttributeMaxDynamicSharedMemorySize, TF_SMEM);

    prep_weights<<<6912, 256>>>(w1, w2, w3);
    im2col_kernel<<<dim3(64, 8, 8), 256>>>(X);

    // conv1: M=pix (im2col rows), N=co (weight rows) -> feat1 [b][pix][co]
    gemm_mma<0><<<dim3(4, 32, 8), 256, GSMEM>>>(
        1, 0LL, KCONV, 9437184LL,     0, 0LL,       KCONV, 0LL,
        KCONV, 0, 1048576LL, 256, b1);
    // conv2 -> feat2 [b][pix][co]
    gemm_mma<0><<<dim3(4, 32, 8), 256, GSMEM>>>(
        1, 0LL, KCONV, 9437184LL,     0, 589824LL,  KCONV, 0LL,
        KCONV, 1, 1048576LL, 256, b2);
    // conv3: M=co, N=pix -> feat3 tf32 [b][co][pix]
    gemm_mma<1><<<dim3(64, 2, 8), 256, GSMEM>>>(
        0, 1179648LL, KCONV, 0LL,     1, 0LL,       KCONV, 9437184LL,
        KCONV, 0, 1048576LL, 4096, b3);

    // logits: S[n][m] = sum_c feat1[n][c] * feat2[m][c]  -> g_M fp32
    gemm_mma<2><<<dim3(64, 32, 8), 256, GSMEM>>>(
        2, 0LL, 256, 1048576LL,       3, 0LL,       256,   1048576LL,
        256, 0, 16777216LL, 4096, b1);

    softmax_kernel<<<BB * NNPIX, 256>>>();

    // final: out[c][n] = alpha * sum_m Df[c][m] * P[n][m]   (tf32 single pass)
    gemm_tf32_final<<<dim3(64, 2, 8), 256, TF_SMEM>>>(out, alpha);
}